// round 6
// baseline (speedup 1.0000x reference)
#include <cuda_runtime.h>
#include <math.h>

// Problem constants
#define BB 2
#define NN 2048
#define BN 4096          // B*N
#define CC 256
#define HI 64
#define WI 176
#define HW (HI*WI)       // 11264
#define TS 16            // tile size
#define TBX (WI/TS)      // 11
#define TBY (HI/TS)      // 4
#define TPB (TBX*TBY)    // 44 tiles per batch
#define NT (BB*TPB)      // 88 tiles total
#define MAXG 2048        // max gaussians per tile (= N per batch)
#define FM_SIZE (BB*CC*HW)

typedef unsigned long long u64;

// ---- f32x2 packed-math helpers (sm_100+/sm_103a) ----
__device__ __forceinline__ void fma2(u64 &acc, u64 a, u64 b) {
    asm("fma.rn.f32x2 %0, %1, %2, %0;" : "+l"(acc) : "l"(a), "l"(b));
}
__device__ __forceinline__ u64 pk2(float lo, float hi) {
    u64 r; asm("mov.b64 %0, {%1, %2};" : "=l"(r) : "f"(lo), "f"(hi)); return r;
}
__device__ __forceinline__ float2 upk(u64 v) {
    float2 r; asm("mov.b64 {%0, %1}, %2;" : "=f"(r.x), "=f"(r.y) : "l"(v)); return r;
}

// ---------------- device scratch ----------------
__device__ float g_h1[BN*64];
__device__ float g_h2[BN*128];
__device__ float g_feats[BN*CC];
__device__ float g_ft1[BN*CC];
__device__ float g_featsT[BN*CC];

__device__ float g_px[BN], g_py[BN], g_isx[BN], g_isy[BN], g_w[BN], g_as[BN];
__device__ int   g_tcount[NT];
__device__ int   g_tlist[NT*MAXG];

// ---------------- projection + binning (fused) ----------------
__global__ void proj_bin_kernel(const float* __restrict__ g, const float* __restrict__ Kin) {
    int i = blockIdx.x * blockDim.x + threadIdx.x;
    if (i >= BN) return;
    const float* gd = g + (size_t)i * 14;
    float x = gd[0], y = gd[1], z = gd[2];
    float k00 = Kin[0], k01 = Kin[1], k02 = Kin[2];
    float k10 = Kin[3], k11 = Kin[4], k12 = Kin[5];
    float k20 = Kin[6], k21 = Kin[7], k22 = Kin[8];
    float pz = k20 * x + k21 * y + k22 * z;
    float denom = pz + 1e-6f;
    float pxn = (k00 * x + k01 * y + k02 * z) / denom;
    float pyn = (k10 * x + k11 * y + k12 * z) / denom;
    float scale_x = (float)WI / k02 * 0.5f;
    float scale_y = (float)HI / k12 * 0.5f;
    float px = pxn * scale_x;
    float py = pyn * scale_y;
    bool valid = (z > 0.1f);
    bool inb = (px >= 0.f) && (px < (float)WI) && (py >= 0.f) && (py < (float)HI);
    bool mask = valid && inb;
    float sx = fmaxf(gd[5] * scale_x, 1.0f);
    float sy = fmaxf(gd[6] * scale_y, 1.0f);
    float w = mask ? gd[12] : 0.0f;
    g_px[i] = px;  g_py[i] = py;
    g_isx[i] = 1.0f / sx;  g_isy[i] = 1.0f / sy;
    g_w[i]  = w;
    g_as[i] = 0.5f * (sx + sy);
    if (w == 0.0f) return;

    // bin into tiles intersecting the 3-sigma bbox
    float rx = 3.0f * sx;
    float ry = 3.0f * sy;
    int b = i >> 11;
    int tx0 = max(0, (int)floorf((px - rx) * (1.0f / TS)));
    int tx1 = min(TBX - 1, (int)floorf((px + rx) * (1.0f / TS)));
    int ty0 = max(0, (int)floorf((py - ry) * (1.0f / TS)));
    int ty1 = min(TBY - 1, (int)floorf((py + ry) * (1.0f / TS)));
    for (int ty = ty0; ty <= ty1; ty++)
        for (int tx = tx0; tx <= tx1; tx++) {
            int t = b * TPB + ty * TBX + tx;
            int o = atomicAdd(&g_tcount[t], 1);
            if (o < MAXG) g_tlist[t * MAXG + o] = i;
        }
}

// ---------------- fp32 GEMM with f32x2 packed FMA ----------------
// C[M x Nd] = act(A[M x Kd] @ W[Kd x Nd] + bias). TILE 64x64, K-tile 16,
// 256 threads, 4x4 microtile computed as 2 M-pairs x 4 N via FFMA2.
// A staged transposed (adjacent M = natural f32x2 pair); W staged as (v,v)
// duplicated 8-byte pairs so one LDS.64 yields a ready broadcast operand.
__global__ void __launch_bounds__(256) gemm_kernel(
    const float* __restrict__ A, const float* __restrict__ Wm,
    const float* __restrict__ bias, float* __restrict__ Cm,
    int Kd, int Nd, int doRelu)
{
    __shared__ __align__(16) float As[16][66];   // [k][m], row stride 66*4=264B (8B-aligned)
    __shared__ __align__(16) u64   Bd[16][64];   // [k][n] duplicated pairs
    int m0 = blockIdx.x * 64;
    int n0 = blockIdx.y * 64;
    int t = threadIdx.x;
    int txq = t & 15;       // N group of 4
    int tyq = t >> 4;       // M group of 4
    u64 acc[2][4];
    #pragma unroll
    for (int i = 0; i < 2; i++)
        #pragma unroll
        for (int j = 0; j < 4; j++) acc[i][j] = 0ull;

    bool fast = ((Kd & 15) == 0);
    for (int k0 = 0; k0 < Kd; k0 += 16) {
        if (fast) {
            // A tile: one float4 per thread, stored transposed
            int mr = t >> 2, kq = (t & 3) * 4;
            float4 a4 = *(const float4*)&A[(size_t)(m0 + mr) * Kd + k0 + kq];
            As[kq + 0][mr] = a4.x; As[kq + 1][mr] = a4.y;
            As[kq + 2][mr] = a4.z; As[kq + 3][mr] = a4.w;
            // W tile: one float4 per thread, stored as dup pairs
            int kk = t >> 4, j4 = (t & 15) * 4;
            float4 w4 = *(const float4*)&Wm[(size_t)(k0 + kk) * Nd + n0 + j4];
            Bd[kk][j4 + 0] = pk2(w4.x, w4.x); Bd[kk][j4 + 1] = pk2(w4.y, w4.y);
            Bd[kk][j4 + 2] = pk2(w4.z, w4.z); Bd[kk][j4 + 3] = pk2(w4.w, w4.w);
        } else {
            int r = t >> 4, c = t & 15;
            #pragma unroll
            for (int it = 0; it < 4; it++) {
                int k = k0 + c;
                As[c][r + it * 16] = (k < Kd) ? A[(size_t)(m0 + r + it * 16) * Kd + k] : 0.f;
            }
            int kk = t >> 6, j = t & 63;
            #pragma unroll
            for (int it = 0; it < 4; it++) {
                int k = k0 + kk + it * 4;
                float w = (k < Kd) ? Wm[(size_t)k * Nd + n0 + j] : 0.f;
                Bd[kk + it * 4][j] = pk2(w, w);
            }
        }
        __syncthreads();
        #pragma unroll
        for (int kk = 0; kk < 16; kk++) {
            const u64* arow = (const u64*)&As[kk][0];
            u64 a01 = arow[tyq * 2];        // rows (4tyq, 4tyq+1)
            u64 a23 = arow[tyq * 2 + 1];    // rows (4tyq+2, 4tyq+3)
            ulonglong2 b01 = *(const ulonglong2*)&Bd[kk][txq * 4];
            ulonglong2 b23 = *(const ulonglong2*)&Bd[kk][txq * 4 + 2];
            fma2(acc[0][0], a01, b01.x); fma2(acc[0][1], a01, b01.y);
            fma2(acc[0][2], a01, b23.x); fma2(acc[0][3], a01, b23.y);
            fma2(acc[1][0], a23, b01.x); fma2(acc[1][1], a23, b01.y);
            fma2(acc[1][2], a23, b23.x); fma2(acc[1][3], a23, b23.y);
        }
        __syncthreads();
    }
    float4 bv = *(const float4*)&bias[n0 + txq * 4];
    #pragma unroll
    for (int mp = 0; mp < 2; mp++) {
        float2 c0 = upk(acc[mp][0]), c1 = upk(acc[mp][1]);
        float2 c2 = upk(acc[mp][2]), c3 = upk(acc[mp][3]);
        float4 lo = make_float4(c0.x + bv.x, c1.x + bv.y, c2.x + bv.z, c3.x + bv.w);
        float4 hi = make_float4(c0.y + bv.x, c1.y + bv.y, c2.y + bv.z, c3.y + bv.w);
        if (doRelu) {
            lo.x = fmaxf(lo.x, 0.f); lo.y = fmaxf(lo.y, 0.f);
            lo.z = fmaxf(lo.z, 0.f); lo.w = fmaxf(lo.w, 0.f);
            hi.x = fmaxf(hi.x, 0.f); hi.y = fmaxf(hi.y, 0.f);
            hi.z = fmaxf(hi.z, 0.f); hi.w = fmaxf(hi.w, 0.f);
        }
        *(float4*)&Cm[(size_t)(m0 + tyq * 4 + mp * 2) * Nd + n0 + txq * 4]     = lo;
        *(float4*)&Cm[(size_t)(m0 + tyq * 4 + mp * 2 + 1) * Nd + n0 + txq * 4] = hi;
    }
}

// ---------------- tile render with fused normalization ----------------
// grid: (NT, 4 channel slices), 256 threads. Each block: 16x16 pixel tile,
// 64 channels. Every slice accumulates density in-register and normalizes
// its channels before the single output write (no finalize passes).
__global__ void __launch_bounds__(256, 2) render_kernel(float* __restrict__ out) {
    int tile = blockIdx.x;
    int slice = blockIdx.y;
    int b = tile / TPB;
    int tl = tile % TPB;
    int tx0 = (tl % TBX) * TS;
    int ty0 = (tl / TBX) * TS;
    int t = threadIdx.x;
    int lx = t & 15;
    int ly = t >> 4;

    __shared__ float s_px[16], s_py[16], s_isx[16], s_isy[16], s_w[16], s_as[16];
    __shared__ int   s_n[16];
    __shared__ float s_ex[16][16], s_ey[16][16], s_dx2[16][16], s_dy2[16][16];
    __shared__ __align__(16) float s_gw[16][256];
    __shared__ __align__(16) u64   s_Fd[16][64];   // feats dup pairs (this slice)
    __shared__ float s_d[256];

    u64 acc[4][8];   // 4 channels x 8 pixel-pairs (16 px)
    #pragma unroll
    for (int i = 0; i < 4; i++)
        #pragma unroll
        for (int q = 0; q < 8; q++) acc[i][q] = 0ull;
    float dacc = 0.f, uacc = 0.f;

    int K = g_tcount[tile];
    if (K > MAXG) K = MAXG;

    for (int c0 = 0; c0 < K; c0 += 16) {
        if (t < 16) {
            int idx = c0 + t;
            if (idx < K) {
                int n = g_tlist[tile * MAXG + idx];
                s_n[t] = n;
                s_px[t] = g_px[n];   s_py[t] = g_py[n];
                s_isx[t] = g_isx[n]; s_isy[t] = g_isy[n];
                s_w[t] = g_w[n];     s_as[t] = g_as[n];
            } else {
                s_n[t] = 0;
                s_px[t] = 3e8f; s_py[t] = 3e8f;
                s_isx[t] = 1.f; s_isy[t] = 1.f;
                s_w[t] = 0.f;   s_as[t] = 0.f;
            }
        }
        __syncthreads();
        // feats slice: 16 gaussians x 64 channels, duplicated pairs
        {
            int j = t >> 4;
            int cidx = (t & 15) * 4;
            int n = s_n[j];
            float4 f = *(const float4*)&g_featsT[(size_t)n * CC + slice * 64 + cidx];
            s_Fd[j][cidx + 0] = pk2(f.x, f.x);
            s_Fd[j][cidx + 1] = pk2(f.y, f.y);
            s_Fd[j][cidx + 2] = pk2(f.z, f.z);
            s_Fd[j][cidx + 3] = pk2(f.w, f.w);
        }
        // separable exp
        {
            int j = t >> 4, i2 = t & 15;
            float dx = ((float)(tx0 + i2) - s_px[j]) * s_isx[j];
            float dx2 = dx * dx;
            s_dx2[j][i2] = dx2;
            s_ex[j][i2] = __expf(-0.5f * dx2);
            float dy = ((float)(ty0 + i2) - s_py[j]) * s_isy[j];
            float dy2 = dy * dy;
            s_dy2[j][i2] = dy2;
            s_ey[j][i2] = __expf(-0.5f * dy2);
        }
        __syncthreads();
        // gw for my pixel across 16 gaussians + density/uncertainty
        #pragma unroll
        for (int j = 0; j < 16; j++) {
            float d = s_dx2[j][lx] + s_dy2[j][ly];
            float gwv = (d < 9.0f) ? s_w[j] * s_ex[j][lx] * s_ey[j][ly] : 0.0f;
            s_gw[j][t] = gwv;
            dacc += gwv;
            uacc += gwv * s_as[j];
        }
        __syncthreads();
        // feature GEMM: acc[ch][pxpair] += F_dup[j][ch] * gw_pair[j][px]
        {
            int cg4 = lx * 4;
            #pragma unroll
            for (int j = 0; j < 16; j++) {
                ulonglong2 f01 = *(const ulonglong2*)&s_Fd[j][cg4];
                ulonglong2 f23 = *(const ulonglong2*)&s_Fd[j][cg4 + 2];
                const ulonglong2* g2 = (const ulonglong2*)&s_gw[j][ly * 16];
                #pragma unroll
                for (int q = 0; q < 4; q++) {
                    ulonglong2 gq = g2[q];
                    fma2(acc[0][q * 2],     f01.x, gq.x);
                    fma2(acc[0][q * 2 + 1], f01.x, gq.y);
                    fma2(acc[1][q * 2],     f01.y, gq.x);
                    fma2(acc[1][q * 2 + 1], f01.y, gq.y);
                    fma2(acc[2][q * 2],     f23.x, gq.x);
                    fma2(acc[2][q * 2 + 1], f23.x, gq.y);
                    fma2(acc[3][q * 2],     f23.y, gq.x);
                    fma2(acc[3][q * 2 + 1], f23.y, gq.y);
                }
            }
        }
        __syncthreads();
    }

    // share density across the tile, normalize, write
    s_d[t] = dacc;
    __syncthreads();
    float inv[16];
    #pragma unroll
    for (int p = 0; p < 16; p++) inv[p] = 1.0f / fmaxf(s_d[ly * 16 + p], 1e-6f);

    int gy = ty0 + ly;
    float* base = out + (((size_t)(b * CC + slice * 64 + lx * 4) * HI + gy) * WI + tx0);
    #pragma unroll
    for (int ci = 0; ci < 4; ci++) {
        float* row = base + (size_t)ci * HW;
        #pragma unroll
        for (int q = 0; q < 8; q += 2) {
            float2 v0 = upk(acc[ci][q]);
            float2 v1 = upk(acc[ci][q + 1]);
            float4 o = make_float4(v0.x * inv[q * 2],     v0.y * inv[q * 2 + 1],
                                   v1.x * inv[q * 2 + 2], v1.y * inv[q * 2 + 3]);
            *(float4*)&row[q * 2] = o;
        }
    }
    if (slice == 0) {
        int pix = gy * WI + tx0 + lx;
        float d = fmaxf(dacc, 1e-6f);
        out[FM_SIZE + b * HW + pix] = uacc / d;                // uncertainty / density
        out[FM_SIZE + BB * HW + b * HW + pix] = d;             // clipped density
    }
}

// ---------------- launch ----------------
extern "C" void kernel_launch(void* const* d_in, const int* in_sizes, int n_in,
                              void* d_out, int out_size) {
    const float* g      = (const float*)d_in[0];
    const float* intr   = (const float*)d_in[1];
    const float* enc_w1 = (const float*)d_in[2];
    const float* enc_b1 = (const float*)d_in[3];
    const float* enc_w2 = (const float*)d_in[4];
    const float* enc_b2 = (const float*)d_in[5];
    const float* enc_w3 = (const float*)d_in[6];
    const float* enc_b3 = (const float*)d_in[7];
    const float* ft_w1  = (const float*)d_in[8];
    const float* ft_b1  = (const float*)d_in[9];
    const float* ft_w2  = (const float*)d_in[10];
    const float* ft_b2  = (const float*)d_in[11];
    float* out = (float*)d_out;

    float *p_h1, *p_h2, *p_feats, *p_ft1, *p_featsT;
    int* p_tcount;
    cudaGetSymbolAddress((void**)&p_h1, g_h1);
    cudaGetSymbolAddress((void**)&p_h2, g_h2);
    cudaGetSymbolAddress((void**)&p_feats, g_feats);
    cudaGetSymbolAddress((void**)&p_ft1, g_ft1);
    cudaGetSymbolAddress((void**)&p_featsT, g_featsT);
    cudaGetSymbolAddress((void**)&p_tcount, g_tcount);

    cudaMemsetAsync(p_tcount, 0, NT * sizeof(int));
    proj_bin_kernel<<<(BN + 255) / 256, 256>>>(g, intr);

    gemm_kernel<<<dim3(BN / 64, 1), 256>>>(g,        enc_w1, enc_b1, p_h1,     14,  64,  1);
    gemm_kernel<<<dim3(BN / 64, 2), 256>>>(p_h1,     enc_w2, enc_b2, p_h2,     64,  128, 1);
    gemm_kernel<<<dim3(BN / 64, 4), 256>>>(p_h2,     enc_w3, enc_b3, p_feats,  128, 256, 0);
    gemm_kernel<<<dim3(BN / 64, 4), 256>>>(p_feats,  ft_w1,  ft_b1,  p_ft1,    256, 256, 1);
    gemm_kernel<<<dim3(BN / 64, 4), 256>>>(p_ft1,    ft_w2,  ft_b2,  p_featsT, 256, 256, 0);

    render_kernel<<<dim3(NT, 4), 256>>>(out);
}

// round 7
// speedup vs baseline: 1.3553x; 1.3553x over previous
#include <cuda_runtime.h>
#include <math.h>

// Problem constants
#define BB 2
#define NN 2048
#define BN 4096          // B*N
#define CC 256
#define HI 64
#define WI 176
#define HW (HI*WI)       // 11264
#define TS 16            // tile size
#define TBX (WI/TS)      // 11
#define TBY (HI/TS)      // 4
#define TPB (TBX*TBY)    // 44 tiles per batch
#define NT (BB*TPB)      // 88 tiles total
#define MAXG 2048        // max gaussians per tile
#define FM_SIZE (BB*CC*HW)
#define NSL 8            // channel slices in render
#define CPS 32           // channels per slice

// ---------------- device scratch ----------------
__device__ float g_h1[BN*64];
__device__ float g_h2[BN*128];
__device__ float g_feats[BN*CC];
__device__ float g_ft1[BN*CC];
__device__ float g_featsT[BN*CC];

__device__ float g_px[BN], g_py[BN], g_isx[BN], g_isy[BN], g_w[BN], g_as[BN];
__device__ int   g_tcount[NT];
__device__ int   g_tlist[NT*MAXG];

// ---------------- projection + binning (fused) ----------------
__global__ void proj_bin_kernel(const float* __restrict__ g, const float* __restrict__ Kin) {
    int i = blockIdx.x * blockDim.x + threadIdx.x;
    if (i >= BN) return;
    const float* gd = g + (size_t)i * 14;
    float x = gd[0], y = gd[1], z = gd[2];
    float k00 = Kin[0], k01 = Kin[1], k02 = Kin[2];
    float k10 = Kin[3], k11 = Kin[4], k12 = Kin[5];
    float k20 = Kin[6], k21 = Kin[7], k22 = Kin[8];
    float pz = k20 * x + k21 * y + k22 * z;
    float denom = pz + 1e-6f;
    float pxn = (k00 * x + k01 * y + k02 * z) / denom;
    float pyn = (k10 * x + k11 * y + k12 * z) / denom;
    float scale_x = (float)WI / k02 * 0.5f;
    float scale_y = (float)HI / k12 * 0.5f;
    float px = pxn * scale_x;
    float py = pyn * scale_y;
    bool valid = (z > 0.1f);
    bool inb = (px >= 0.f) && (px < (float)WI) && (py >= 0.f) && (py < (float)HI);
    bool mask = valid && inb;
    float sx = fmaxf(gd[5] * scale_x, 1.0f);
    float sy = fmaxf(gd[6] * scale_y, 1.0f);
    float w = mask ? gd[12] : 0.0f;
    g_px[i] = px;  g_py[i] = py;
    g_isx[i] = 1.0f / sx;  g_isy[i] = 1.0f / sy;
    g_w[i]  = w;
    g_as[i] = 0.5f * (sx + sy);
    if (w == 0.0f) return;

    float rx = 3.0f * sx;
    float ry = 3.0f * sy;
    int b = i >> 11;
    int tx0 = max(0, (int)floorf((px - rx) * (1.0f / TS)));
    int tx1 = min(TBX - 1, (int)floorf((px + rx) * (1.0f / TS)));
    int ty0 = max(0, (int)floorf((py - ry) * (1.0f / TS)));
    int ty1 = min(TBY - 1, (int)floorf((py + ry) * (1.0f / TS)));
    for (int ty = ty0; ty <= ty1; ty++)
        for (int tx = tx0; tx <= tx1; tx++) {
            int t = b * TPB + ty * TBX + tx;
            int o = atomicAdd(&g_tcount[t], 1);
            if (o < MAXG) g_tlist[t * MAXG + o] = i;
        }
}

// ---------------- fp32 GEMM (R4 structure, 16B-aligned A rows) ----------------
// C = act(A[MxK] @ W[KxN] + b). TILE 64x64, K-tile 16, 256 threads, 4x4 microtile.
__global__ void __launch_bounds__(256) gemm_kernel(
    const float* __restrict__ A, const float* __restrict__ Wm,
    const float* __restrict__ bias, float* __restrict__ Cm,
    int Kd, int Nd, int doRelu)
{
    __shared__ __align__(16) float As[16][68];   // row stride 272B = 17*16B
    __shared__ __align__(16) float Bs[16][64];
    int m0 = blockIdx.x * 64;
    int n0 = blockIdx.y * 64;
    int t = threadIdx.x;
    int txq = t & 15;
    int tyq = t >> 4;
    float acc[4][4];
    #pragma unroll
    for (int i = 0; i < 4; i++)
        #pragma unroll
        for (int j = 0; j < 4; j++) acc[i][j] = 0.f;

    for (int k0 = 0; k0 < Kd; k0 += 16) {
        {
            int r = t >> 4, c = t & 15;
            #pragma unroll
            for (int it = 0; it < 4; it++) {
                int k = k0 + c;
                As[c][r + it * 16] = (k < Kd) ? A[(size_t)(m0 + r + it * 16) * Kd + k] : 0.f;
            }
        }
        {
            int kk = t >> 6, j = t & 63;
            #pragma unroll
            for (int it = 0; it < 4; it++) {
                int k = k0 + kk + it * 4;
                Bs[kk + it * 4][j] = (k < Kd) ? Wm[(size_t)k * Nd + n0 + j] : 0.f;
            }
        }
        __syncthreads();
        #pragma unroll
        for (int kk = 0; kk < 16; kk++) {
            float4 aq = *(const float4*)&As[kk][tyq * 4];   // 1 LDS.128
            float4 bq = *(const float4*)&Bs[kk][txq * 4];   // 1 LDS.128
            acc[0][0] += aq.x * bq.x; acc[0][1] += aq.x * bq.y; acc[0][2] += aq.x * bq.z; acc[0][3] += aq.x * bq.w;
            acc[1][0] += aq.y * bq.x; acc[1][1] += aq.y * bq.y; acc[1][2] += aq.y * bq.z; acc[1][3] += aq.y * bq.w;
            acc[2][0] += aq.z * bq.x; acc[2][1] += aq.z * bq.y; acc[2][2] += aq.z * bq.z; acc[2][3] += aq.z * bq.w;
            acc[3][0] += aq.w * bq.x; acc[3][1] += aq.w * bq.y; acc[3][2] += aq.w * bq.z; acc[3][3] += aq.w * bq.w;
        }
        __syncthreads();
    }
    float4 bv = *(const float4*)&bias[n0 + txq * 4];
    #pragma unroll
    for (int i = 0; i < 4; i++) {
        float4 o;
        o.x = acc[i][0] + bv.x; o.y = acc[i][1] + bv.y;
        o.z = acc[i][2] + bv.z; o.w = acc[i][3] + bv.w;
        if (doRelu) {
            o.x = fmaxf(o.x, 0.f); o.y = fmaxf(o.y, 0.f);
            o.z = fmaxf(o.z, 0.f); o.w = fmaxf(o.w, 0.f);
        }
        *(float4*)&Cm[(size_t)(m0 + tyq * 4 + i) * Nd + n0 + txq * 4] = o;
    }
}

// ---------------- tile render: 8 slices x 32 channels, fused normalization ----
// grid (NT, 8), 256 threads. Thread roles:
//  - gw/density: pixel t (lx = t&15, ly = t>>4)
//  - accumulate: channel group chg = t&7 (4 ch), pixel range pr = t>>3
//                (prow = pr>>1, phalf = pr&1 -> 8 pixels)
__global__ void __launch_bounds__(256, 2) render_kernel(float* __restrict__ out) {
    int tile = blockIdx.x;
    int slice = blockIdx.y;
    int b = tile / TPB;
    int tl = tile % TPB;
    int tx0 = (tl % TBX) * TS;
    int ty0 = (tl / TBX) * TS;
    int t = threadIdx.x;
    int lx = t & 15;
    int ly = t >> 4;
    int chg = t & 7;
    int pr = t >> 3;
    int prow = pr >> 1;
    int phalf = pr & 1;

    __shared__ float s_px[16], s_py[16], s_isx[16], s_isy[16], s_w[16], s_as[16];
    __shared__ int   s_n[16];
    __shared__ float s_ex[16][16], s_ey[16][16], s_dx2[16][16], s_dy2[16][16];
    __shared__ __align__(16) float s_gw[16][256];
    __shared__ __align__(16) float s_F[16][CPS];
    __shared__ float s_d[256];

    float acc[4][8];
    #pragma unroll
    for (int i = 0; i < 4; i++)
        #pragma unroll
        for (int p = 0; p < 8; p++) acc[i][p] = 0.f;
    float dacc = 0.f, uacc = 0.f;

    int K = g_tcount[tile];
    if (K > MAXG) K = MAXG;

    for (int c0 = 0; c0 < K; c0 += 16) {
        if (t < 16) {
            int idx = c0 + t;
            if (idx < K) {
                int n = g_tlist[tile * MAXG + idx];
                s_n[t] = n;
                s_px[t] = g_px[n];   s_py[t] = g_py[n];
                s_isx[t] = g_isx[n]; s_isy[t] = g_isy[n];
                s_w[t] = g_w[n];     s_as[t] = g_as[n];
            } else {
                s_n[t] = 0;
                s_px[t] = 3e8f; s_py[t] = 3e8f;
                s_isx[t] = 1.f; s_isy[t] = 1.f;
                s_w[t] = 0.f;   s_as[t] = 0.f;
            }
        }
        __syncthreads();
        // feats slice: 16 gaussians x 32 channels (128 threads, one float4 each)
        if (t < 128) {
            int j = t >> 3;
            int ci = (t & 7) * 4;
            int n = s_n[j];
            float4 f = *(const float4*)&g_featsT[(size_t)n * CC + slice * CPS + ci];
            *(float4*)&s_F[j][ci] = f;
        }
        // separable exp
        {
            int j = t >> 4, i2 = t & 15;
            float dx = ((float)(tx0 + i2) - s_px[j]) * s_isx[j];
            float dx2 = dx * dx;
            s_dx2[j][i2] = dx2;
            s_ex[j][i2] = __expf(-0.5f * dx2);
            float dy = ((float)(ty0 + i2) - s_py[j]) * s_isy[j];
            float dy2 = dy * dy;
            s_dy2[j][i2] = dy2;
            s_ey[j][i2] = __expf(-0.5f * dy2);
        }
        __syncthreads();
        // gw for my pixel across 16 gaussians + density/uncertainty
        #pragma unroll
        for (int j = 0; j < 16; j++) {
            float d = s_dx2[j][lx] + s_dy2[j][ly];
            float gwv = (d < 9.0f) ? s_w[j] * s_ex[j][lx] * s_ey[j][ly] : 0.0f;
            s_gw[j][t] = gwv;
            dacc += gwv;
            uacc += gwv * s_as[j];
        }
        __syncthreads();
        // feature accumulate: acc[ci][pp] += F[j][chg*4+ci] * gw[j][prow*16+phalf*8+pp]
        {
            const int pbase = prow * 16 + phalf * 8;
            #pragma unroll
            for (int j = 0; j < 16; j++) {
                float4 f = *(const float4*)&s_F[j][chg * 4];
                const float* gwr = &s_gw[j][pbase];
                #pragma unroll
                for (int pp = 0; pp < 8; pp += 4) {
                    float4 g4 = *(const float4*)&gwr[pp];
                    acc[0][pp + 0] += f.x * g4.x; acc[0][pp + 1] += f.x * g4.y;
                    acc[0][pp + 2] += f.x * g4.z; acc[0][pp + 3] += f.x * g4.w;
                    acc[1][pp + 0] += f.y * g4.x; acc[1][pp + 1] += f.y * g4.y;
                    acc[1][pp + 2] += f.y * g4.z; acc[1][pp + 3] += f.y * g4.w;
                    acc[2][pp + 0] += f.z * g4.x; acc[2][pp + 1] += f.z * g4.y;
                    acc[2][pp + 2] += f.z * g4.z; acc[2][pp + 3] += f.z * g4.w;
                    acc[3][pp + 0] += f.w * g4.x; acc[3][pp + 1] += f.w * g4.y;
                    acc[3][pp + 2] += f.w * g4.z; acc[3][pp + 3] += f.w * g4.w;
                }
            }
        }
        __syncthreads();
    }

    // share density, normalize, single write
    s_d[t] = dacc;
    __syncthreads();
    const int pbase = prow * 16 + phalf * 8;
    float inv[8];
    #pragma unroll
    for (int p = 0; p < 8; p++) inv[p] = 1.0f / fmaxf(s_d[pbase + p], 1e-6f);

    int gy = ty0 + prow;
    float* base = out + (((size_t)(b * CC + slice * CPS + chg * 4) * HI + gy) * WI + tx0 + phalf * 8);
    #pragma unroll
    for (int ci = 0; ci < 4; ci++) {
        float* row = base + (size_t)ci * HW;
        #pragma unroll
        for (int pp = 0; pp < 8; pp += 4) {
            float4 o = make_float4(acc[ci][pp + 0] * inv[pp + 0],
                                   acc[ci][pp + 1] * inv[pp + 1],
                                   acc[ci][pp + 2] * inv[pp + 2],
                                   acc[ci][pp + 3] * inv[pp + 3]);
            *(float4*)&row[pp] = o;
        }
    }
    if (slice == 0) {
        int pix = (ty0 + ly) * WI + tx0 + lx;
        float d = fmaxf(dacc, 1e-6f);
        out[FM_SIZE + b * HW + pix] = uacc / d;        // uncertainty / density
        out[FM_SIZE + BB * HW + b * HW + pix] = d;     // clipped density
    }
}

// ---------------- launch ----------------
extern "C" void kernel_launch(void* const* d_in, const int* in_sizes, int n_in,
                              void* d_out, int out_size) {
    const float* g      = (const float*)d_in[0];
    const float* intr   = (const float*)d_in[1];
    const float* enc_w1 = (const float*)d_in[2];
    const float* enc_b1 = (const float*)d_in[3];
    const float* enc_w2 = (const float*)d_in[4];
    const float* enc_b2 = (const float*)d_in[5];
    const float* enc_w3 = (const float*)d_in[6];
    const float* enc_b3 = (const float*)d_in[7];
    const float* ft_w1  = (const float*)d_in[8];
    const float* ft_b1  = (const float*)d_in[9];
    const float* ft_w2  = (const float*)d_in[10];
    const float* ft_b2  = (const float*)d_in[11];
    float* out = (float*)d_out;

    float *p_h1, *p_h2, *p_feats, *p_ft1, *p_featsT;
    int* p_tcount;
    cudaGetSymbolAddress((void**)&p_h1, g_h1);
    cudaGetSymbolAddress((void**)&p_h2, g_h2);
    cudaGetSymbolAddress((void**)&p_feats, g_feats);
    cudaGetSymbolAddress((void**)&p_ft1, g_ft1);
    cudaGetSymbolAddress((void**)&p_featsT, g_featsT);
    cudaGetSymbolAddress((void**)&p_tcount, g_tcount);

    cudaMemsetAsync(p_tcount, 0, NT * sizeof(int));
    proj_bin_kernel<<<(BN + 255) / 256, 256>>>(g, intr);

    gemm_kernel<<<dim3(BN / 64, 1), 256>>>(g,        enc_w1, enc_b1, p_h1,     14,  64,  1);
    gemm_kernel<<<dim3(BN / 64, 2), 256>>>(p_h1,     enc_w2, enc_b2, p_h2,     64,  128, 1);
    gemm_kernel<<<dim3(BN / 64, 4), 256>>>(p_h2,     enc_w3, enc_b3, p_feats,  128, 256, 0);
    gemm_kernel<<<dim3(BN / 64, 4), 256>>>(p_feats,  ft_w1,  ft_b1,  p_ft1,    256, 256, 1);
    gemm_kernel<<<dim3(BN / 64, 4), 256>>>(p_ft1,    ft_w2,  ft_b2,  p_featsT, 256, 256, 0);

    render_kernel<<<dim3(NT, NSL), 256>>>(out);
}